// round 7
// baseline (speedup 1.0000x reference)
#include <cuda_runtime.h>
#include <cuda_bf16.h>
#include <cstdint>

#define BB 256
#define NN 256
#define MM 256
#define DD 1024
#define RBAND 128
#define BIGF 1e30f

// dist row-major [b][i][j]
__device__ float g_dist[(size_t)BB * 256 * 256];

static __device__ __forceinline__ uint32_t smem_u32(const void* p) {
    uint32_t a;
    asm("{ .reg .u64 t; cvta.to.shared.u64 t, %1; cvt.u32.u64 %0, t; }" : "=r"(a) : "l"(p));
    return a;
}
static __device__ __forceinline__ void ldsm_x4(uint32_t& r0, uint32_t& r1, uint32_t& r2,
                                               uint32_t& r3, uint32_t addr) {
    asm volatile("ldmatrix.sync.aligned.m8n8.x4.shared.b16 {%0,%1,%2,%3}, [%4];"
                 : "=r"(r0), "=r"(r1), "=r"(r2), "=r"(r3) : "r"(addr));
}
static __device__ __forceinline__ uint2 cvt_f4_bf16(float4 a) {
    __nv_bfloat162 p0 = __floats2bfloat162_rn(a.x, a.y);
    __nv_bfloat162 p1 = __floats2bfloat162_rn(a.z, a.w);
    uint2 w;
    w.x = *reinterpret_cast<unsigned int*>(&p0);
    w.y = *reinterpret_cast<unsigned int*>(&p1);
    return w;
}

// ---------------------------------------------------------------------------
// Fused kernel (R4 config — known good): normalization + batched GEMM.
// Grid (2,2,B), 128x128 tile, 256 thr (8 warps: 2M x 4N), warp tile 64x32,
// K-tile 32, double-buffered smem pad-40, ldmatrix fragments, occupancy 2.
// Per-row sum-of-squares accumulated during fp32 loads; epilogue applies
// 1/(|x||y|), clamps, stores dist row-major as float2.
// ---------------------------------------------------------------------------
#define KT 32
#define LDP 40

__global__ __launch_bounds__(256, 2) void gemm_kernel(const float* __restrict__ s1,
                                                      const float* __restrict__ s2) {
    __shared__ __nv_bfloat16 As[2][128 * LDP];
    __shared__ __nv_bfloat16 Bs[2][128 * LDP];
    __shared__ float invA_s[128];
    __shared__ float invB_s[128];

    int b  = blockIdx.z;
    int i0 = blockIdx.x * 128;
    int j0 = blockIdx.y * 128;
    int t    = threadIdx.x;
    int lane = t & 31;
    int w    = t >> 5;
    int wm = w & 1;
    int wn = w >> 1;
    int gid = lane >> 2;
    int tig = lane & 3;

    const float* Ag = s1 + (size_t)b * NN * DD + (size_t)i0 * DD;
    const float* Bg = s2 + (size_t)b * MM * DD + (size_t)j0 * DD;

    int lr = t >> 3;
    int lc = (t & 7) * 4;

    float acc[4][4][4];
#pragma unroll
    for (int mt = 0; mt < 4; mt++)
#pragma unroll
        for (int nt = 0; nt < 4; nt++)
#pragma unroll
            for (int c = 0; c < 4; c++) acc[mt][nt][c] = 0.f;

    float ssA[4] = {0.f, 0.f, 0.f, 0.f};
    float ssB[4] = {0.f, 0.f, 0.f, 0.f};

    uint2 ra[4], rb[4];
#pragma unroll
    for (int r4 = 0; r4 < 4; r4++) {
        float4 a4 = *(const float4*)(Ag + (size_t)(lr + r4 * 32) * DD + lc);
        float4 b4 = *(const float4*)(Bg + (size_t)(lr + r4 * 32) * DD + lc);
        ssA[r4] += a4.x * a4.x + a4.y * a4.y + a4.z * a4.z + a4.w * a4.w;
        ssB[r4] += b4.x * b4.x + b4.y * b4.y + b4.z * b4.z + b4.w * b4.w;
        ra[r4] = cvt_f4_bf16(a4);
        rb[r4] = cvt_f4_bf16(b4);
    }
    int buf = 0;
#pragma unroll
    for (int r4 = 0; r4 < 4; r4++) {
        *(uint2*)&As[buf][(lr + r4 * 32) * LDP + lc] = ra[r4];
        *(uint2*)&Bs[buf][(lr + r4 * 32) * LDP + lc] = rb[r4];
    }
    __syncthreads();

    int a_row_in = (lane & 15);
    int a_koff   = (lane >> 4) * 8;
    int b_row_in = ((lane >> 4) << 3) + (lane & 7);
    int b_koff   = ((lane >> 3) & 1) * 8;

    for (int kt = 0; kt < DD / KT; kt++) {
        int nk = kt + 1;
        if (nk < DD / KT) {
#pragma unroll
            for (int r4 = 0; r4 < 4; r4++) {
                float4 a4 = *(const float4*)(Ag + (size_t)(lr + r4 * 32) * DD + nk * KT + lc);
                float4 b4 = *(const float4*)(Bg + (size_t)(lr + r4 * 32) * DD + nk * KT + lc);
                ssA[r4] += a4.x * a4.x + a4.y * a4.y + a4.z * a4.z + a4.w * a4.w;
                ssB[r4] += b4.x * b4.x + b4.y * b4.y + b4.z * b4.z + b4.w * b4.w;
                ra[r4] = cvt_f4_bf16(a4);
                rb[r4] = cvt_f4_bf16(b4);
            }
        }
#pragma unroll
        for (int kk = 0; kk < KT; kk += 16) {
            uint32_t af[4][4];
            uint32_t bf2[2][4];
#pragma unroll
            for (int mt = 0; mt < 4; mt++) {
                int arow = wm * 64 + mt * 16 + a_row_in;
                uint32_t addr = smem_u32(&As[buf][arow * LDP + kk + a_koff]);
                ldsm_x4(af[mt][0], af[mt][1], af[mt][2], af[mt][3], addr);
            }
#pragma unroll
            for (int ntp = 0; ntp < 2; ntp++) {
                int brow = wn * 32 + ntp * 16 + b_row_in;
                uint32_t addr = smem_u32(&Bs[buf][brow * LDP + kk + b_koff]);
                ldsm_x4(bf2[ntp][0], bf2[ntp][1], bf2[ntp][2], bf2[ntp][3], addr);
            }
#pragma unroll
            for (int mt = 0; mt < 4; mt++)
#pragma unroll
                for (int nt = 0; nt < 4; nt++) {
                    uint32_t b0 = bf2[nt >> 1][(nt & 1) * 2];
                    uint32_t b1 = bf2[nt >> 1][(nt & 1) * 2 + 1];
                    asm volatile(
                        "mma.sync.aligned.m16n8k16.row.col.f32.bf16.bf16.f32 "
                        "{%0,%1,%2,%3}, {%4,%5,%6,%7}, {%8,%9}, {%0,%1,%2,%3};\n"
                        : "+f"(acc[mt][nt][0]), "+f"(acc[mt][nt][1]),
                          "+f"(acc[mt][nt][2]), "+f"(acc[mt][nt][3])
                        : "r"(af[mt][0]), "r"(af[mt][1]), "r"(af[mt][2]), "r"(af[mt][3]),
                          "r"(b0), "r"(b1));
                }
        }
        if (nk < DD / KT) {
            int nbuf = buf ^ 1;
#pragma unroll
            for (int r4 = 0; r4 < 4; r4++) {
                *(uint2*)&As[nbuf][(lr + r4 * 32) * LDP + lc] = ra[r4];
                *(uint2*)&Bs[nbuf][(lr + r4 * 32) * LDP + lc] = rb[r4];
            }
        }
        __syncthreads();
        buf ^= 1;
    }

#pragma unroll
    for (int r4 = 0; r4 < 4; r4++) {
#pragma unroll
        for (int o = 1; o < 8; o <<= 1) {
            ssA[r4] += __shfl_xor_sync(0xffffffffu, ssA[r4], o);
            ssB[r4] += __shfl_xor_sync(0xffffffffu, ssB[r4], o);
        }
        if ((lane & 7) == 0) {
            int row = lr + r4 * 32;
            invA_s[row] = 1.0f / fmaxf(sqrtf(ssA[r4]), 1e-12f);
            invB_s[row] = 1.0f / fmaxf(sqrtf(ssB[r4]), 1e-12f);
        }
    }
    __syncthreads();

    float* dT = g_dist + (size_t)b * 65536;
#pragma unroll
    for (int mt = 0; mt < 4; mt++) {
#pragma unroll
        for (int nt = 0; nt < 4; nt++) {
            int li = wm * 64 + mt * 16 + gid;
            int lj = wn * 32 + nt * 8 + tig * 2;
            float ia0 = invA_s[li];
            float ia1 = invA_s[li + 8];
            float ib0 = invB_s[lj];
            float ib1 = invB_s[lj + 1];
            float2 v0, v1;
            v0.x = 1.0f - fminf(fmaxf(acc[mt][nt][0] * ia0 * ib0, -1.f), 1.f);
            v0.y = 1.0f - fminf(fmaxf(acc[mt][nt][1] * ia0 * ib1, -1.f), 1.f);
            v1.x = 1.0f - fminf(fmaxf(acc[mt][nt][2] * ia1 * ib0, -1.f), 1.f);
            v1.y = 1.0f - fminf(fmaxf(acc[mt][nt][3] * ia1 * ib1, -1.f), 1.f);
            int i = i0 + li;
            int j = j0 + lj;
            *(float2*)&dT[(size_t)i * 256 + j]       = v0;
            *(float2*)&dT[(size_t)(i + 8) * 256 + j] = v1;
        }
    }
}

// ---------------------------------------------------------------------------
// Kernel 2: banded DTW, SKEWED systolic wavefront. Lane L processes row
// r = t - L at step t, owning columns [8L, 8L+8). Cross-lane deps (col 8L-1 of
// rows r, r-1) were computed by lane L-1 at steps t-1/t-2 -> one shfl.up pair
// of committed registers; NO warp scan. Virtual row -1 = BIG makes row 0 the
// cumsum case automatically. 4-deep register ring of row slices (dist is
// L2-resident straight after the GEMM).
// ---------------------------------------------------------------------------
__global__ __launch_bounds__(128) void dtw_kernel(float* __restrict__ out) {
    int w     = threadIdx.x >> 5;
    int lane  = threadIdx.x & 31;
    int batch = blockIdx.x * 4 + w;
    const float* E = g_dist + (size_t)batch * 65536;
    int jb = lane * 8;

    float d1[8];
#pragma unroll
    for (int u = 0; u < 8; u++) d1[u] = BIGF;
    float last7 = BIGF, prev7 = BIGF;
    float result = 0.f;

    float4 pf[4][2];
    // prologue: slots for steps 0..3 (row r = p - lane, valid iff lane <= p)
#pragma unroll
    for (int p = 0; p < 4; p++) {
        int r = p - lane;
        if (r >= 0) {
            const float* src = E + (size_t)r * 256 + jb;
            pf[p][0] = *(const float4*)src;
            pf[p][1] = *(const float4*)(src + 4);
        }
    }

#pragma unroll 1
    for (int tb = 0; tb < 288; tb += 4) {
#pragma unroll
        for (int p = 0; p < 4; p++) {
            int t = tb + p;
            int r = t - lane;
            bool act = (r >= 0) && (r < 256);

            float e[8];
            e[0] = pf[p][0].x; e[1] = pf[p][0].y; e[2] = pf[p][0].z; e[3] = pf[p][0].w;
            e[4] = pf[p][1].x; e[5] = pf[p][1].y; e[6] = pf[p][1].z; e[7] = pf[p][1].w;

            // refill slot p with row r+4 (consumed at step t+4)
            int rl = r + 4;
            if (rl >= 0 && rl < 256) {
                const float* src = E + (size_t)rl * 256 + jb;
                pf[p][0] = *(const float4*)src;
                pf[p][1] = *(const float4*)(src + 4);
            }

            // neighbor values from lane L-1 (committed at earlier steps)
            float lf0 = __shfl_up_sync(0xffffffffu, last7, 1);  // (r,   jb-1)
            float ul0 = __shfl_up_sync(0xffffffffu, prev7, 1);  // (r-1, jb-1)

            float m[8];
            m[0] = fminf(d1[0], ul0);
#pragma unroll
            for (int u = 1; u < 8; u++) m[u] = fminf(d1[u], d1[u - 1]);

            float nv[8];
            if (lane == 0) {
                // col 0: row0 -> d; rows 1..RBAND -> up + d; else BIG
                nv[0] = (r == 0) ? e[0] : ((r <= RBAND) ? d1[0] + e[0] : BIGF);
            } else {
                bool ib = (jb >= r - RBAND) && (jb <= r + RBAND);
                nv[0] = ib ? fminf(m[0], lf0) + e[0] : BIGF;
            }
#pragma unroll
            for (int u = 1; u < 8; u++) {
                int j = jb + u;
                bool ib = (j >= r - RBAND) && (j <= r + RBAND);
                nv[u] = ib ? fminf(m[u], nv[u - 1]) + e[u] : BIGF;
            }

            if (act) {
#pragma unroll
                for (int u = 0; u < 8; u++) d1[u] = nv[u];
                prev7 = last7;
                last7 = nv[7];
                if (r == 255) result = nv[7];
            }
        }
    }

    if (lane == 31) out[batch] = result;
}

// ---------------------------------------------------------------------------
extern "C" void kernel_launch(void* const* d_in, const int* in_sizes, int n_in,
                              void* d_out, int out_size) {
    const float* s1 = (const float*)d_in[0];
    const float* s2 = (const float*)d_in[1];
    float* out = (float*)d_out;

    dim3 g(2, 2, BB);
    gemm_kernel<<<g, 256>>>(s1, s2);

    dtw_kernel<<<64, 128>>>(out);
}

// round 8
// speedup vs baseline: 1.1118x; 1.1118x over previous
#include <cuda_runtime.h>
#include <cuda_bf16.h>
#include <cstdint>

#define BB 256
#define NN 256
#define MM 256
#define DD 1024
#define RBAND 128
#define BIGF 1e30f

// dist row-major [b][i][j]
__device__ float g_dist[(size_t)BB * 256 * 256];

static __device__ __forceinline__ uint32_t smem_u32(const void* p) {
    uint32_t a;
    asm("{ .reg .u64 t; cvta.to.shared.u64 t, %1; cvt.u32.u64 %0, t; }" : "=r"(a) : "l"(p));
    return a;
}
static __device__ __forceinline__ void cp16(uint32_t dst, const void* src) {
    asm volatile("cp.async.cg.shared.global [%0], [%1], 16;\n" ::"r"(dst), "l"(src) : "memory");
}
static __device__ __forceinline__ void ldsm_x4(uint32_t& r0, uint32_t& r1, uint32_t& r2,
                                               uint32_t& r3, uint32_t addr) {
    asm volatile("ldmatrix.sync.aligned.m8n8.x4.shared.b16 {%0,%1,%2,%3}, [%4];"
                 : "=r"(r0), "=r"(r1), "=r"(r2), "=r"(r3) : "r"(addr));
}
static __device__ __forceinline__ uint2 cvt_f4_bf16(float4 a) {
    __nv_bfloat162 p0 = __floats2bfloat162_rn(a.x, a.y);
    __nv_bfloat162 p1 = __floats2bfloat162_rn(a.z, a.w);
    uint2 w;
    w.x = *reinterpret_cast<unsigned int*>(&p0);
    w.y = *reinterpret_cast<unsigned int*>(&p1);
    return w;
}

// ---------------------------------------------------------------------------
// Fused kernel (R4 config — known good): normalization + batched GEMM.
// ---------------------------------------------------------------------------
#define KT 32
#define LDP 40

__global__ __launch_bounds__(256, 2) void gemm_kernel(const float* __restrict__ s1,
                                                      const float* __restrict__ s2) {
    __shared__ __nv_bfloat16 As[2][128 * LDP];
    __shared__ __nv_bfloat16 Bs[2][128 * LDP];
    __shared__ float invA_s[128];
    __shared__ float invB_s[128];

    int b  = blockIdx.z;
    int i0 = blockIdx.x * 128;
    int j0 = blockIdx.y * 128;
    int t    = threadIdx.x;
    int lane = t & 31;
    int w    = t >> 5;
    int wm = w & 1;
    int wn = w >> 1;
    int gid = lane >> 2;
    int tig = lane & 3;

    const float* Ag = s1 + (size_t)b * NN * DD + (size_t)i0 * DD;
    const float* Bg = s2 + (size_t)b * MM * DD + (size_t)j0 * DD;

    int lr = t >> 3;
    int lc = (t & 7) * 4;

    float acc[4][4][4];
#pragma unroll
    for (int mt = 0; mt < 4; mt++)
#pragma unroll
        for (int nt = 0; nt < 4; nt++)
#pragma unroll
            for (int c = 0; c < 4; c++) acc[mt][nt][c] = 0.f;

    float ssA[4] = {0.f, 0.f, 0.f, 0.f};
    float ssB[4] = {0.f, 0.f, 0.f, 0.f};

    uint2 ra[4], rb[4];
#pragma unroll
    for (int r4 = 0; r4 < 4; r4++) {
        float4 a4 = *(const float4*)(Ag + (size_t)(lr + r4 * 32) * DD + lc);
        float4 b4 = *(const float4*)(Bg + (size_t)(lr + r4 * 32) * DD + lc);
        ssA[r4] += a4.x * a4.x + a4.y * a4.y + a4.z * a4.z + a4.w * a4.w;
        ssB[r4] += b4.x * b4.x + b4.y * b4.y + b4.z * b4.z + b4.w * b4.w;
        ra[r4] = cvt_f4_bf16(a4);
        rb[r4] = cvt_f4_bf16(b4);
    }
    int buf = 0;
#pragma unroll
    for (int r4 = 0; r4 < 4; r4++) {
        *(uint2*)&As[buf][(lr + r4 * 32) * LDP + lc] = ra[r4];
        *(uint2*)&Bs[buf][(lr + r4 * 32) * LDP + lc] = rb[r4];
    }
    __syncthreads();

    int a_row_in = (lane & 15);
    int a_koff   = (lane >> 4) * 8;
    int b_row_in = ((lane >> 4) << 3) + (lane & 7);
    int b_koff   = ((lane >> 3) & 1) * 8;

    for (int kt = 0; kt < DD / KT; kt++) {
        int nk = kt + 1;
        if (nk < DD / KT) {
#pragma unroll
            for (int r4 = 0; r4 < 4; r4++) {
                float4 a4 = *(const float4*)(Ag + (size_t)(lr + r4 * 32) * DD + nk * KT + lc);
                float4 b4 = *(const float4*)(Bg + (size_t)(lr + r4 * 32) * DD + nk * KT + lc);
                ssA[r4] += a4.x * a4.x + a4.y * a4.y + a4.z * a4.z + a4.w * a4.w;
                ssB[r4] += b4.x * b4.x + b4.y * b4.y + b4.z * b4.z + b4.w * b4.w;
                ra[r4] = cvt_f4_bf16(a4);
                rb[r4] = cvt_f4_bf16(b4);
            }
        }
#pragma unroll
        for (int kk = 0; kk < KT; kk += 16) {
            uint32_t af[4][4];
            uint32_t bf2[2][4];
#pragma unroll
            for (int mt = 0; mt < 4; mt++) {
                int arow = wm * 64 + mt * 16 + a_row_in;
                uint32_t addr = smem_u32(&As[buf][arow * LDP + kk + a_koff]);
                ldsm_x4(af[mt][0], af[mt][1], af[mt][2], af[mt][3], addr);
            }
#pragma unroll
            for (int ntp = 0; ntp < 2; ntp++) {
                int brow = wn * 32 + ntp * 16 + b_row_in;
                uint32_t addr = smem_u32(&Bs[buf][brow * LDP + kk + b_koff]);
                ldsm_x4(bf2[ntp][0], bf2[ntp][1], bf2[ntp][2], bf2[ntp][3], addr);
            }
#pragma unroll
            for (int mt = 0; mt < 4; mt++)
#pragma unroll
                for (int nt = 0; nt < 4; nt++) {
                    uint32_t b0 = bf2[nt >> 1][(nt & 1) * 2];
                    uint32_t b1 = bf2[nt >> 1][(nt & 1) * 2 + 1];
                    asm volatile(
                        "mma.sync.aligned.m16n8k16.row.col.f32.bf16.bf16.f32 "
                        "{%0,%1,%2,%3}, {%4,%5,%6,%7}, {%8,%9}, {%0,%1,%2,%3};\n"
                        : "+f"(acc[mt][nt][0]), "+f"(acc[mt][nt][1]),
                          "+f"(acc[mt][nt][2]), "+f"(acc[mt][nt][3])
                        : "r"(af[mt][0]), "r"(af[mt][1]), "r"(af[mt][2]), "r"(af[mt][3]),
                          "r"(b0), "r"(b1));
                }
        }
        if (nk < DD / KT) {
            int nbuf = buf ^ 1;
#pragma unroll
            for (int r4 = 0; r4 < 4; r4++) {
                *(uint2*)&As[nbuf][(lr + r4 * 32) * LDP + lc] = ra[r4];
                *(uint2*)&Bs[nbuf][(lr + r4 * 32) * LDP + lc] = rb[r4];
            }
        }
        __syncthreads();
        buf ^= 1;
    }

#pragma unroll
    for (int r4 = 0; r4 < 4; r4++) {
#pragma unroll
        for (int o = 1; o < 8; o <<= 1) {
            ssA[r4] += __shfl_xor_sync(0xffffffffu, ssA[r4], o);
            ssB[r4] += __shfl_xor_sync(0xffffffffu, ssB[r4], o);
        }
        if ((lane & 7) == 0) {
            int row = lr + r4 * 32;
            invA_s[row] = 1.0f / fmaxf(sqrtf(ssA[r4]), 1e-12f);
            invB_s[row] = 1.0f / fmaxf(sqrtf(ssB[r4]), 1e-12f);
        }
    }
    __syncthreads();

    float* dT = g_dist + (size_t)b * 65536;
#pragma unroll
    for (int mt = 0; mt < 4; mt++) {
#pragma unroll
        for (int nt = 0; nt < 4; nt++) {
            int li = wm * 64 + mt * 16 + gid;
            int lj = wn * 32 + nt * 8 + tig * 2;
            float ia0 = invA_s[li];
            float ia1 = invA_s[li + 8];
            float ib0 = invB_s[lj];
            float ib1 = invB_s[lj + 1];
            float2 v0, v1;
            v0.x = 1.0f - fminf(fmaxf(acc[mt][nt][0] * ia0 * ib0, -1.f), 1.f);
            v0.y = 1.0f - fminf(fmaxf(acc[mt][nt][1] * ia0 * ib1, -1.f), 1.f);
            v1.x = 1.0f - fminf(fmaxf(acc[mt][nt][2] * ia1 * ib0, -1.f), 1.f);
            v1.y = 1.0f - fminf(fmaxf(acc[mt][nt][3] * ia1 * ib1, -1.f), 1.f);
            int i = i0 + li;
            int j = j0 + lj;
            *(float2*)&dT[(size_t)i * 256 + j]       = v0;
            *(float2*)&dT[(size_t)(i + 8) * 256 + j] = v1;
        }
    }
}

// ---------------------------------------------------------------------------
// Kernel 2: banded DTW — systolic staircase compute (R7-verified cell math,
// no warp scan) + R4-proven cp.async ring pipework. Lane L processes row
// r = t - L at step t. Rows live 32 steps -> ring depth 40 (32 + 8 prefetch
// lead). One commit-group per row; wait_group 7 == row t resident (read slots
// are 8..39 groups old). One warp per batch, 256 CTAs.
// ---------------------------------------------------------------------------
#define RDEPTH 40

__global__ __launch_bounds__(32) void dtw_kernel(float* __restrict__ out) {
    __shared__ float ring[RDEPTH][256];
    int lane  = threadIdx.x & 31;
    int batch = blockIdx.x;
    const float* E = g_dist + (size_t)batch * 65536;
    int jb = lane * 8;

    // prologue: rows 0..7, one commit group each
    for (int s = 0; s < 8; s++) {
        uint32_t sa = smem_u32(&ring[s][jb]);
        const float* src = E + (size_t)s * 256 + jb;
        cp16(sa, src);
        cp16(sa + 16, src + 4);
        asm volatile("cp.async.commit_group;\n" ::: "memory");
    }

    float d1[8];
#pragma unroll
    for (int u = 0; u < 8; u++) d1[u] = BIGF;
    float last7 = BIGF, prev7 = BIGF;
    float result = 0.f;

    int sr = (RDEPTH - lane) % RDEPTH;  // slot of row (t - lane) at t=0
    int sw = 8;                         // slot of row (t + 8) at t=0

#pragma unroll 4
    for (int t = 0; t < 288; t++) {
        int r = t - lane;
        bool act = (r >= 0) && (r < 256);

        asm volatile("cp.async.wait_group 7;\n" ::: "memory");

        float e[8];
        {
            const float* slot = &ring[sr][jb];
            float4 q0 = *(const float4*)(slot);
            float4 q1 = *(const float4*)(slot + 4);
            e[0] = q0.x; e[1] = q0.y; e[2] = q0.z; e[3] = q0.w;
            e[4] = q1.x; e[5] = q1.y; e[6] = q1.z; e[7] = q1.w;
        }

        // prefetch row t+8 into slot sw; one commit group per step regardless
        {
            int rl = t + 8;
            if (rl < 256) {
                uint32_t sa = smem_u32(&ring[sw][jb]);
                const float* src = E + (size_t)rl * 256 + jb;
                cp16(sa, src);
                cp16(sa + 16, src + 4);
            }
            asm volatile("cp.async.commit_group;\n" ::: "memory");
        }

        // neighbor values from lane L-1 (committed at steps t-1 / t-2)
        float lf0 = __shfl_up_sync(0xffffffffu, last7, 1);  // (r,   jb-1)
        float ul0 = __shfl_up_sync(0xffffffffu, prev7, 1);  // (r-1, jb-1)

        float m[8];
        m[0] = fminf(d1[0], ul0);
#pragma unroll
        for (int u = 1; u < 8; u++) m[u] = fminf(d1[u], d1[u - 1]);

        float nv[8];
        if (lane == 0) {
            nv[0] = (r == 0) ? e[0] : ((r <= RBAND) ? d1[0] + e[0] : BIGF);
        } else {
            bool ib = (jb >= r - RBAND) && (jb <= r + RBAND);
            nv[0] = ib ? fminf(m[0], lf0) + e[0] : BIGF;
        }
#pragma unroll
        for (int u = 1; u < 8; u++) {
            int j = jb + u;
            bool ib = (j >= r - RBAND) && (j <= r + RBAND);
            nv[u] = ib ? fminf(m[u], nv[u - 1]) + e[u] : BIGF;
        }

        if (act) {
#pragma unroll
            for (int u = 0; u < 8; u++) d1[u] = nv[u];
            prev7 = last7;
            last7 = nv[7];
            if (r == 255) result = nv[7];
        }

        sr = (sr + 1 == RDEPTH) ? 0 : sr + 1;
        sw = (sw + 1 == RDEPTH) ? 0 : sw + 1;
    }

    if (lane == 31) out[batch] = result;
}

// ---------------------------------------------------------------------------
extern "C" void kernel_launch(void* const* d_in, const int* in_sizes, int n_in,
                              void* d_out, int out_size) {
    const float* s1 = (const float*)d_in[0];
    const float* s2 = (const float*)d_in[1];
    float* out = (float*)d_out;

    dim3 g(2, 2, BB);
    gemm_kernel<<<g, 256>>>(s1, s2);

    dtw_kernel<<<256, 32>>>(out);
}

// round 9
// speedup vs baseline: 1.3872x; 1.2478x over previous
#include <cuda_runtime.h>
#include <cuda_bf16.h>
#include <cstdint>

#define BB 256
#define NN 256
#define MM 256
#define DD 1024
#define RBAND 128
#define BIGF 1e30f

// dist row-major [b][i][j]
__device__ float g_dist[(size_t)BB * 256 * 256];

static __device__ __forceinline__ uint32_t smem_u32(const void* p) {
    uint32_t a;
    asm("{ .reg .u64 t; cvta.to.shared.u64 t, %1; cvt.u32.u64 %0, t; }" : "=r"(a) : "l"(p));
    return a;
}
static __device__ __forceinline__ void cp16(uint32_t dst, const void* src) {
    asm volatile("cp.async.cg.shared.global [%0], [%1], 16;\n" ::"r"(dst), "l"(src) : "memory");
}
static __device__ __forceinline__ void ldsm_x4(uint32_t& r0, uint32_t& r1, uint32_t& r2,
                                               uint32_t& r3, uint32_t addr) {
    asm volatile("ldmatrix.sync.aligned.m8n8.x4.shared.b16 {%0,%1,%2,%3}, [%4];"
                 : "=r"(r0), "=r"(r1), "=r"(r2), "=r"(r3) : "r"(addr));
}
static __device__ __forceinline__ uint2 cvt_f4_bf16(float4 a) {
    __nv_bfloat162 p0 = __floats2bfloat162_rn(a.x, a.y);
    __nv_bfloat162 p1 = __floats2bfloat162_rn(a.z, a.w);
    uint2 w;
    w.x = *reinterpret_cast<unsigned int*>(&p0);
    w.y = *reinterpret_cast<unsigned int*>(&p1);
    return w;
}

// ---------------------------------------------------------------------------
// Fused kernel: normalization + batched GEMM (R4 config), with the global
// loads HELD IN REGISTERS across the MMA block: LDG issued at top of the
// k-iteration, first use (ss/convert/smem store) at the bottom -> ~500 cyc of
// MMA/LDSM work covers the DRAM latency instead of stalling at the top.
// ---------------------------------------------------------------------------
#define KT 32
#define LDP 40

__global__ __launch_bounds__(256, 2) void gemm_kernel(const float* __restrict__ s1,
                                                      const float* __restrict__ s2) {
    __shared__ __nv_bfloat16 As[2][128 * LDP];
    __shared__ __nv_bfloat16 Bs[2][128 * LDP];
    __shared__ float invA_s[128];
    __shared__ float invB_s[128];

    int b  = blockIdx.z;
    int i0 = blockIdx.x * 128;
    int j0 = blockIdx.y * 128;
    int t    = threadIdx.x;
    int lane = t & 31;
    int w    = t >> 5;
    int wm = w & 1;
    int wn = w >> 1;
    int gid = lane >> 2;
    int tig = lane & 3;

    const float* Ag = s1 + (size_t)b * NN * DD + (size_t)i0 * DD;
    const float* Bg = s2 + (size_t)b * MM * DD + (size_t)j0 * DD;

    int lr = t >> 3;
    int lc = (t & 7) * 4;

    float acc[4][4][4];
#pragma unroll
    for (int mt = 0; mt < 4; mt++)
#pragma unroll
        for (int nt = 0; nt < 4; nt++)
#pragma unroll
            for (int c = 0; c < 4; c++) acc[mt][nt][c] = 0.f;

    float ssA[4] = {0.f, 0.f, 0.f, 0.f};
    float ssB[4] = {0.f, 0.f, 0.f, 0.f};

    // Prologue: load k-tile 0, convert, store to buf 0.
    float4 fa[4], fb[4];
#pragma unroll
    for (int r4 = 0; r4 < 4; r4++) {
        fa[r4] = *(const float4*)(Ag + (size_t)(lr + r4 * 32) * DD + lc);
        fb[r4] = *(const float4*)(Bg + (size_t)(lr + r4 * 32) * DD + lc);
    }
    int buf = 0;
#pragma unroll
    for (int r4 = 0; r4 < 4; r4++) {
        ssA[r4] += fa[r4].x * fa[r4].x + fa[r4].y * fa[r4].y + fa[r4].z * fa[r4].z + fa[r4].w * fa[r4].w;
        ssB[r4] += fb[r4].x * fb[r4].x + fb[r4].y * fb[r4].y + fb[r4].z * fb[r4].z + fb[r4].w * fb[r4].w;
        *(uint2*)&As[buf][(lr + r4 * 32) * LDP + lc] = cvt_f4_bf16(fa[r4]);
        *(uint2*)&Bs[buf][(lr + r4 * 32) * LDP + lc] = cvt_f4_bf16(fb[r4]);
    }
    __syncthreads();

    int a_row_in = (lane & 15);
    int a_koff   = (lane >> 4) * 8;
    int b_row_in = ((lane >> 4) << 3) + (lane & 7);
    int b_koff   = ((lane >> 3) & 1) * 8;

    for (int kt = 0; kt < DD / KT; kt++) {
        int nk = kt + 1;
        // Issue next-tile loads; NO use here (consumed after the MMA block).
        if (nk < DD / KT) {
#pragma unroll
            for (int r4 = 0; r4 < 4; r4++) {
                fa[r4] = *(const float4*)(Ag + (size_t)(lr + r4 * 32) * DD + nk * KT + lc);
                fb[r4] = *(const float4*)(Bg + (size_t)(lr + r4 * 32) * DD + nk * KT + lc);
            }
        }
#pragma unroll
        for (int kk = 0; kk < KT; kk += 16) {
            uint32_t af[4][4];
            uint32_t bf2[2][4];
#pragma unroll
            for (int mt = 0; mt < 4; mt++) {
                int arow = wm * 64 + mt * 16 + a_row_in;
                uint32_t addr = smem_u32(&As[buf][arow * LDP + kk + a_koff]);
                ldsm_x4(af[mt][0], af[mt][1], af[mt][2], af[mt][3], addr);
            }
#pragma unroll
            for (int ntp = 0; ntp < 2; ntp++) {
                int brow = wn * 32 + ntp * 16 + b_row_in;
                uint32_t addr = smem_u32(&Bs[buf][brow * LDP + kk + b_koff]);
                ldsm_x4(bf2[ntp][0], bf2[ntp][1], bf2[ntp][2], bf2[ntp][3], addr);
            }
#pragma unroll
            for (int mt = 0; mt < 4; mt++)
#pragma unroll
                for (int nt = 0; nt < 4; nt++) {
                    uint32_t b0 = bf2[nt >> 1][(nt & 1) * 2];
                    uint32_t b1 = bf2[nt >> 1][(nt & 1) * 2 + 1];
                    asm volatile(
                        "mma.sync.aligned.m16n8k16.row.col.f32.bf16.bf16.f32 "
                        "{%0,%1,%2,%3}, {%4,%5,%6,%7}, {%8,%9}, {%0,%1,%2,%3};\n"
                        : "+f"(acc[mt][nt][0]), "+f"(acc[mt][nt][1]),
                          "+f"(acc[mt][nt][2]), "+f"(acc[mt][nt][3])
                        : "r"(af[mt][0]), "r"(af[mt][1]), "r"(af[mt][2]), "r"(af[mt][3]),
                          "r"(b0), "r"(b1));
                }
        }
        // First use of the loads: ss accumulation + convert + smem store.
        if (nk < DD / KT) {
            int nbuf = buf ^ 1;
#pragma unroll
            for (int r4 = 0; r4 < 4; r4++) {
                ssA[r4] += fa[r4].x * fa[r4].x + fa[r4].y * fa[r4].y + fa[r4].z * fa[r4].z + fa[r4].w * fa[r4].w;
                ssB[r4] += fb[r4].x * fb[r4].x + fb[r4].y * fb[r4].y + fb[r4].z * fb[r4].z + fb[r4].w * fb[r4].w;
                *(uint2*)&As[nbuf][(lr + r4 * 32) * LDP + lc] = cvt_f4_bf16(fa[r4]);
                *(uint2*)&Bs[nbuf][(lr + r4 * 32) * LDP + lc] = cvt_f4_bf16(fb[r4]);
            }
        }
        __syncthreads();
        buf ^= 1;
    }

#pragma unroll
    for (int r4 = 0; r4 < 4; r4++) {
#pragma unroll
        for (int o = 1; o < 8; o <<= 1) {
            ssA[r4] += __shfl_xor_sync(0xffffffffu, ssA[r4], o);
            ssB[r4] += __shfl_xor_sync(0xffffffffu, ssB[r4], o);
        }
        if ((lane & 7) == 0) {
            int row = lr + r4 * 32;
            invA_s[row] = 1.0f / fmaxf(sqrtf(ssA[r4]), 1e-12f);
            invB_s[row] = 1.0f / fmaxf(sqrtf(ssB[r4]), 1e-12f);
        }
    }
    __syncthreads();

    float* dT = g_dist + (size_t)b * 65536;
#pragma unroll
    for (int mt = 0; mt < 4; mt++) {
#pragma unroll
        for (int nt = 0; nt < 4; nt++) {
            int li = wm * 64 + mt * 16 + gid;
            int lj = wn * 32 + nt * 8 + tig * 2;
            float ia0 = invA_s[li];
            float ia1 = invA_s[li + 8];
            float ib0 = invB_s[lj];
            float ib1 = invB_s[lj + 1];
            float2 v0, v1;
            v0.x = 1.0f - fminf(fmaxf(acc[mt][nt][0] * ia0 * ib0, -1.f), 1.f);
            v0.y = 1.0f - fminf(fmaxf(acc[mt][nt][1] * ia0 * ib1, -1.f), 1.f);
            v1.x = 1.0f - fminf(fmaxf(acc[mt][nt][2] * ia1 * ib0, -1.f), 1.f);
            v1.y = 1.0f - fminf(fmaxf(acc[mt][nt][3] * ia1 * ib1, -1.f), 1.f);
            int i = i0 + li;
            int j = j0 + lj;
            *(float2*)&dT[(size_t)i * 256 + j]       = v0;
            *(float2*)&dT[(size_t)(i + 8) * 256 + j] = v1;
        }
    }
}

// ---------------------------------------------------------------------------
// Kernel 2: banded DTW, row-streaming min-plus scan (R4 exact — 68 us known).
// ---------------------------------------------------------------------------
#define SDEPTH 8

__global__ __launch_bounds__(128) void dtw_kernel(float* __restrict__ out) {
    __shared__ float ring[4][SDEPTH][256];
    int w     = threadIdx.x >> 5;
    int lane  = threadIdx.x & 31;
    int batch = blockIdx.x * 4 + w;
    const float* E = g_dist + (size_t)batch * 65536;
    int cbase = lane * 8;

    for (int s = 0; s < SDEPTH; s++) {
        uint32_t sa = smem_u32(&ring[w][s][cbase]);
        const float* src = E + (size_t)s * 256 + cbase;
        cp16(sa, src);
        cp16(sa + 16, src + 4);
        asm volatile("cp.async.commit_group;\n" ::: "memory");
    }

    float prev[8];

    for (int r = 0; r < 256; r++) {
        asm volatile("cp.async.wait_group 7;\n" ::: "memory");
        float e[8];
        const float* slot = &ring[w][r & (SDEPTH - 1)][cbase];
#pragma unroll
        for (int u = 0; u < 8; u++) e[u] = slot[u];

        int nr = r + SDEPTH;
        if (nr < 256) {
            uint32_t sa = smem_u32(&ring[w][nr & (SDEPTH - 1)][cbase]);
            const float* src = E + (size_t)nr * 256 + cbase;
            cp16(sa, src);
            cp16(sa + 16, src + 4);
        }
        asm volatile("cp.async.commit_group;\n" ::: "memory");

        if (r == 0) {
            float ps[8];
            float run = 0.f;
#pragma unroll
            for (int u = 0; u < 8; u++) { run += e[u]; ps[u] = run; }
            float acc = run;
#pragma unroll
            for (int d = 1; d < 32; d <<= 1) {
                float p = __shfl_up_sync(0xffffffffu, acc, d);
                if (lane >= d) acc += p;
            }
            float excl = acc - run;
#pragma unroll
            for (int u = 0; u < 8; u++) {
                float tv = excl + ps[u];
                prev[u] = (cbase + u <= RBAND) ? tv : BIGF;
            }
        } else {
            float pl = __shfl_up_sync(0xffffffffu, prev[7], 1);
            if (lane == 0) pl = BIGF;
            float bb[8], ss[8];
#pragma unroll
            for (int u = 0; u < 8; u++) {
                int c = cbase + u;
                float pjm1 = u ? prev[u - 1] : pl;
                bool ib = (c >= 1) && (c >= r - RBAND) && (c <= r + RBAND);
                bb[u] = ib ? fminf(prev[u], pjm1) + e[u] : BIGF;
                ss[u] = ib ? e[u] : BIGF;
            }
            if (lane == 0) {
                bb[0] = (r <= RBAND) ? prev[0] + e[0] : BIGF;
                ss[0] = BIGF;
            }
            float tl[8], P[8];
            tl[0] = bb[0];
            P[0]  = ss[0];
#pragma unroll
            for (int u = 1; u < 8; u++) {
                tl[u] = fminf(bb[u], tl[u - 1] + ss[u]);
                P[u]  = P[u - 1] + ss[u];
            }
            float S = P[7], T = tl[7];
#pragma unroll
            for (int d = 1; d < 32; d <<= 1) {
                float Sp = __shfl_up_sync(0xffffffffu, S, d);
                float Tp = __shfl_up_sync(0xffffffffu, T, d);
                if (lane >= d) {
                    T = fminf(T, Tp + S);
                    S = S + Sp;
                }
            }
            float cin = __shfl_up_sync(0xffffffffu, T, 1);
            if (lane == 0) cin = BIGF;
#pragma unroll
            for (int u = 0; u < 8; u++) prev[u] = fminf(tl[u], cin + P[u]);
        }
    }

    if (lane == 31) out[batch] = prev[7];
}

// ---------------------------------------------------------------------------
extern "C" void kernel_launch(void* const* d_in, const int* in_sizes, int n_in,
                              void* d_out, int out_size) {
    const float* s1 = (const float*)d_in[0];
    const float* s2 = (const float*)d_in[1];
    float* out = (float*)d_out;

    dim3 g(2, 2, BB);
    gemm_kernel<<<g, 256>>>(s1, s2);

    dtw_kernel<<<64, 128>>>(out);
}